// round 1
// baseline (speedup 1.0000x reference)
#include <cuda_runtime.h>
#include <math.h>
#include <stdint.h>

// Problem dims
#define BB   32
#define TT   64
#define VV   30000
#define EMBD 512
#define HID  512
#define ED   256
#define XD   768    // EMB + E
#define G4   2048   // 4*H

// ---------------- scratch (device globals; no allocation allowed) -------------
__device__ __align__(16) float g_X [2048 * 768];    // [B*T, EMB+E]
__device__ __align__(16) float g_pg[2048 * 2048];   // pregates [B*T, 4H]
__device__ __align__(16) float g_H [2048 * 512];    // all hidden states [B*T, H]
__device__ __align__(16) float g_hA[512 * 32];      // h transposed [H, B] (ping)
__device__ __align__(16) float g_hB[512 * 32];      // h transposed [H, B] (pong)
__device__ __align__(16) float g_cT[512 * 32];      // c transposed [H, B]

// ---------------- prep: build X = [emb(captions) || encoder_out], zero h,c ----
__global__ void prep_kernel(const float* __restrict__ enc,
                            const int*   __restrict__ captions,
                            const float* __restrict__ emb_table,
                            float* __restrict__ X,
                            float* __restrict__ h0,
                            float* __restrict__ c0)
{
    int blk = blockIdx.x;
    if (blk < 2048) {
        int r = blk;           // r = b*T + t
        int b = r >> 6;        // /T
        int cap = captions[r];
        const float* erow = emb_table + (size_t)cap * EMBD;
        const float* crow = enc + (size_t)b * ED;
        float* xrow = X + (size_t)r * XD;
        for (int c = threadIdx.x; c < XD; c += blockDim.x) {
            xrow[c] = (c < EMBD) ? erow[c] : crow[c - EMBD];
        }
    } else {
        // zero h0 (16384 floats) and c0 (16384 floats); 32 blocks x 256 threads
        int i = (blk - 2048) * 256 + threadIdx.x;   // 0..8191
        for (int j = i; j < 16384; j += 8192) {
            h0[j] = 0.0f;
            c0[j] = 0.0f;
        }
    }
}

// ---------------- generic NT GEMM: C[M,N] = A[M,K] * B[N,K]^T + bias ----------
// A row-major [M,K], B row-major [N,K]. M multiple of 128, K multiple of 16.
// N may be ragged (guarded).
#define BM 128
#define BN 128
#define BK 16
__global__ __launch_bounds__(256, 2)
void gemm_nt_kernel(const float* __restrict__ A,
                    const float* __restrict__ Bm,
                    float* __restrict__ C,
                    const float* __restrict__ bias0,
                    const float* __restrict__ bias1,
                    int M, int N, int K)
{
    __shared__ float As[BK][BM + 4];
    __shared__ float Bs[BK][BN + 4];

    const int n0 = blockIdx.x * BN;
    const int m0 = blockIdx.y * BM;
    const int tid = threadIdx.x;
    const int tx = tid & 15;        // 0..15 -> n micro
    const int ty = tid >> 4;        // 0..15 -> m micro

    float acc[8][8];
#pragma unroll
    for (int i = 0; i < 8; i++)
#pragma unroll
        for (int j = 0; j < 8; j++) acc[i][j] = 0.0f;

    for (int kt = 0; kt < K; kt += BK) {
        // Load A tile: 128 rows x 16 k = 512 float4; 2 per thread
#pragma unroll
        for (int i = 0; i < 2; i++) {
            int a = tid * 2 + i;
            int row = a >> 2;
            int kq  = (a & 3) << 2;
            float4 v = *(const float4*)(A + (size_t)(m0 + row) * K + kt + kq);
            As[kq + 0][row] = v.x;
            As[kq + 1][row] = v.y;
            As[kq + 2][row] = v.z;
            As[kq + 3][row] = v.w;
        }
        // Load B tile with N guard
#pragma unroll
        for (int i = 0; i < 2; i++) {
            int a = tid * 2 + i;
            int row = a >> 2;
            int kq  = (a & 3) << 2;
            int gn  = n0 + row;
            float4 v = make_float4(0.f, 0.f, 0.f, 0.f);
            if (gn < N) v = *(const float4*)(Bm + (size_t)gn * K + kt + kq);
            Bs[kq + 0][row] = v.x;
            Bs[kq + 1][row] = v.y;
            Bs[kq + 2][row] = v.z;
            Bs[kq + 3][row] = v.w;
        }
        __syncthreads();

#pragma unroll
        for (int k = 0; k < BK; k++) {
            float4 a0 = *(const float4*)&As[k][ty * 8];
            float4 a1 = *(const float4*)&As[k][ty * 8 + 4];
            float4 b0 = *(const float4*)&Bs[k][tx * 8];
            float4 b1 = *(const float4*)&Bs[k][tx * 8 + 4];
            float av[8] = {a0.x, a0.y, a0.z, a0.w, a1.x, a1.y, a1.z, a1.w};
            float bv[8] = {b0.x, b0.y, b0.z, b0.w, b1.x, b1.y, b1.z, b1.w};
#pragma unroll
            for (int i = 0; i < 8; i++)
#pragma unroll
                for (int j = 0; j < 8; j++)
                    acc[i][j] = fmaf(av[i], bv[j], acc[i][j]);
        }
        __syncthreads();
    }

    // Epilogue
#pragma unroll
    for (int i = 0; i < 8; i++) {
        int m = m0 + ty * 8 + i;
        float* crow = C + (size_t)m * N;
#pragma unroll
        for (int j = 0; j < 8; j++) {
            int n = n0 + tx * 8 + j;
            if (n < N) {
                float bvv = bias0 ? bias0[n] : 0.0f;
                if (bias1) bvv += bias1[n];
                crow[n] = acc[i][j] + bvv;
            }
        }
    }
}

// ---------------- LSTM step ---------------------------------------------------
// gates[b, j] = pregates[b, t, j] + sum_k h_in[k, b] * W_hh[j, k]
// CTA owns 4 hidden columns (n) x all 32 b x 4 gates -> fully local pointwise.
// grid = 128 CTAs, 64 threads.
__device__ __forceinline__ float sigf(float x) { return 1.0f / (1.0f + expf(-x)); }

__global__ __launch_bounds__(64)
void lstm_step_kernel(const float* __restrict__ pregates,
                      const float* __restrict__ W_hh,
                      const float* __restrict__ h_in,   // [512,32] transposed
                      float* __restrict__ h_out,        // [512,32] transposed
                      float* __restrict__ cT,           // [512,32] transposed
                      float* __restrict__ Hall,         // [B*T, 512]
                      int t)
{
    __shared__ float Ws[16][128];     // 16 gate rows x KCHUNK
    __shared__ float hs[128][36];     // KCHUNK x B (padded)
    __shared__ float gsm[16][33];     // gate exchange

    const int nb  = blockIdx.x * 4;   // n base (0..508)
    const int tid = threadIdx.x;      // 0..63
    const int rp  = tid >> 3;         // row pair 0..7
    const int bg  = tid & 7;          // b group (4 b each)

    float acc0[4] = {0.f, 0.f, 0.f, 0.f};
    float acc1[4] = {0.f, 0.f, 0.f, 0.f};

    for (int kc = 0; kc < HID; kc += 128) {
        // stage W rows: 16 rows x 128 floats = 512 float4
        for (int i = tid; i < 512; i += 64) {
            int rr = i >> 5;          // row 0..15
            int kq = i & 31;          // float4 within row
            int gate = rr >> 2, nl = rr & 3;
            int j = gate * HID + nb + nl;
            *(float4*)&Ws[rr][kq * 4] =
                *(const float4*)&W_hh[(size_t)j * HID + kc + kq * 4];
        }
        // stage h: 128 k x 32 b = 1024 float4
        for (int i = tid; i < 1024; i += 64) {
            int kk = i >> 3;
            int b4 = (i & 7) * 4;
            *(float4*)&hs[kk][b4] = *(const float4*)&h_in[(kc + kk) * 32 + b4];
        }
        __syncthreads();

#pragma unroll 4
        for (int k = 0; k < 128; k += 4) {
            float4 w0 = *(const float4*)&Ws[2 * rp][k];
            float4 w1 = *(const float4*)&Ws[2 * rp + 1][k];
            float wa0[4] = {w0.x, w0.y, w0.z, w0.w};
            float wa1[4] = {w1.x, w1.y, w1.z, w1.w};
#pragma unroll
            for (int kk = 0; kk < 4; kk++) {
                float4 hv = *(const float4*)&hs[k + kk][bg * 4];
                acc0[0] = fmaf(wa0[kk], hv.x, acc0[0]);
                acc0[1] = fmaf(wa0[kk], hv.y, acc0[1]);
                acc0[2] = fmaf(wa0[kk], hv.z, acc0[2]);
                acc0[3] = fmaf(wa0[kk], hv.w, acc0[3]);
                acc1[0] = fmaf(wa1[kk], hv.x, acc1[0]);
                acc1[1] = fmaf(wa1[kk], hv.y, acc1[1]);
                acc1[2] = fmaf(wa1[kk], hv.z, acc1[2]);
                acc1[3] = fmaf(wa1[kk], hv.w, acc1[3]);
            }
        }
        __syncthreads();
    }

    // exchange gate partials
#pragma unroll
    for (int i = 0; i < 4; i++) {
        gsm[2 * rp][bg * 4 + i]     = acc0[i];
        gsm[2 * rp + 1][bg * 4 + i] = acc1[i];
    }
    __syncthreads();

    // pointwise LSTM: 128 (b, nl) pairs
    for (int p = tid; p < 128; p += 64) {
        int b  = p >> 2;
        int nl = p & 3;
        int n  = nb + nl;
        size_t pgbase = ((size_t)b * TT + t) * G4;
        float gi = gsm[0 + nl][b]  + pregates[pgbase + 0 * HID + n];
        float gf = gsm[4 + nl][b]  + pregates[pgbase + 1 * HID + n];
        float gg = gsm[8 + nl][b]  + pregates[pgbase + 2 * HID + n];
        float go = gsm[12 + nl][b] + pregates[pgbase + 3 * HID + n];

        float c_old = cT[n * 32 + b];
        float c_new = sigf(gf) * c_old + sigf(gi) * tanhf(gg);
        float h_new = sigf(go) * tanhf(c_new);

        cT[n * 32 + b]    = c_new;
        h_out[n * 32 + b] = h_new;
        Hall[((size_t)b * TT + t) * HID + n] = h_new;
    }
}

// ---------------- launch ------------------------------------------------------
extern "C" void kernel_launch(void* const* d_in, const int* in_sizes, int n_in,
                              void* d_out, int out_size)
{
    // input order (metadata): encoder_out, captions, We, be, Wd, bd, Wf, bf,
    //                         emb_table, W_ih, W_hh, b_ih, b_hh, W_fc, b_fc
    const float* enc       = (const float*)d_in[0];
    const int*   captions  = (const int*)  d_in[1];
    const float* emb_table = (const float*)d_in[8];
    const float* W_ih      = (const float*)d_in[9];
    const float* W_hh      = (const float*)d_in[10];
    const float* b_ih      = (const float*)d_in[11];
    const float* b_hh      = (const float*)d_in[12];
    const float* W_fc      = (const float*)d_in[13];
    const float* b_fc      = (const float*)d_in[14];
    float* out = (float*)d_out;

    float *pX, *pPG, *pH, *phA, *phB, *pC;
    cudaGetSymbolAddress((void**)&pX,  g_X);
    cudaGetSymbolAddress((void**)&pPG, g_pg);
    cudaGetSymbolAddress((void**)&pH,  g_H);
    cudaGetSymbolAddress((void**)&phA, g_hA);
    cudaGetSymbolAddress((void**)&phB, g_hB);
    cudaGetSymbolAddress((void**)&pC,  g_cT);

    // 1) build X, zero h/c   (attention is identity: context == encoder_out)
    prep_kernel<<<2080, 256>>>(enc, captions, emb_table, pX, phA, pC);

    // 2) pregates = X @ W_ih^T + b_ih + b_hh   [2048 x 2048], K=768
    {
        dim3 grid(G4 / BN, 2048 / BM);
        gemm_nt_kernel<<<grid, 256>>>(pX, W_ih, pPG, b_ih, b_hh,
                                      2048, G4, XD);
    }

    // 3) sequential LSTM over T steps (ping-pong h buffers)
    for (int t = 0; t < TT; t++) {
        float* hin  = (t & 1) ? phB : phA;
        float* hout = (t & 1) ? phA : phB;
        lstm_step_kernel<<<128, 64>>>(pPG, W_hh, hin, hout, pC, pH, t);
    }

    // 4) out = H_all @ W_fc^T + b_fc   [2048 x 30000], K=512
    {
        dim3 grid((VV + BN - 1) / BN, 2048 / BM);
        gemm_nt_kernel<<<grid, 256>>>(pH, W_fc, out, b_fc, nullptr,
                                      2048, VV, HID);
    }
}

// round 3
// speedup vs baseline: 2.0276x; 2.0276x over previous
#include <cuda_runtime.h>
#include <cuda_bf16.h>
#include <math.h>
#include <stdint.h>

// Problem dims
#define TT   64
#define VV   30000
#define HID  512
#define XD   768          // EMB + E
#define G4   2048         // 4*H
#define MROWS 2048        // B*T
#define KX3  (3 * XD)     // 2304
#define KH3  (3 * HID)    // 1536

// ---------------- scratch (device globals; no allocation allowed) -------------
__device__ __align__(16) __nv_bfloat16 g_X3  [MROWS * KX3];   // [Xh|Xh|Xl]
__device__ __align__(16) __nv_bfloat16 g_Wih3[G4 * KX3];      // [Wh|Wl|Wh]
__device__ __align__(16) __nv_bfloat16 g_Wfc3[(size_t)VV * KH3]; // [Wh|Wl|Wh]
__device__ __align__(16) __nv_bfloat16 g_H3  [MROWS * KH3];   // [Hh|Hh|Hl]
__device__ __align__(16) float g_pg[MROWS * G4];
__device__ __align__(16) float g_hA[HID * 32];
__device__ __align__(16) float g_hB[HID * 32];
__device__ int g_bar;

// ---------------- small helpers ------------------------------------------------
__device__ __forceinline__ uint32_t smem_u32(const void* p) {
    uint32_t a;
    asm("{ .reg .u64 t; cvta.to.shared.u64 t, %1; cvt.u32.u64 %0, t; }" : "=r"(a) : "l"(p));
    return a;
}
__device__ __forceinline__ void ldsm4(uint32_t* r, uint32_t addr) {
    asm volatile("ldmatrix.sync.aligned.m8n8.x4.shared.b16 {%0,%1,%2,%3}, [%4];"
                 : "=r"(r[0]), "=r"(r[1]), "=r"(r[2]), "=r"(r[3]) : "r"(addr));
}
__device__ __forceinline__ void mma16816(float* d, const uint32_t* a,
                                         uint32_t b0, uint32_t b1) {
    asm volatile("mma.sync.aligned.m16n8k16.row.col.f32.bf16.bf16.f32 "
                 "{%0,%1,%2,%3}, {%4,%5,%6,%7}, {%8,%9}, {%0,%1,%2,%3};"
                 : "+f"(d[0]), "+f"(d[1]), "+f"(d[2]), "+f"(d[3])
                 : "r"(a[0]), "r"(a[1]), "r"(a[2]), "r"(a[3]), "r"(b0), "r"(b1));
}
__device__ __forceinline__ void cpasync16(uint32_t dst, const void* src) {
    asm volatile("cp.async.cg.shared.global [%0], [%1], 16;" :: "r"(dst), "l"(src));
}
__device__ __forceinline__ void cpasync16z(uint32_t dst, const void* src, unsigned sz) {
    asm volatile("cp.async.cg.shared.global [%0], [%1], 16, %2;"
                 :: "r"(dst), "l"(src), "r"(sz));
}
#define CP_COMMIT() asm volatile("cp.async.commit_group;" ::: "memory")

// ---------------- split weights: src fp32 [R,K] -> dst bf16 [R,3K] = [h|l|h] ---
__global__ void split3b_kernel(const float* __restrict__ src,
                               __nv_bfloat16* __restrict__ dst,
                               int K2, int total2)   // K2 = K/2
{
    int i = blockIdx.x * 256 + threadIdx.x;
    if (i >= total2) return;
    int r = i / K2, cc = i - r * K2;
    float2 v = ((const float2*)src)[i];
    __nv_bfloat16 h0 = __float2bfloat16(v.x), h1 = __float2bfloat16(v.y);
    __nv_bfloat16 l0 = __float2bfloat16(v.x - __bfloat162float(h0));
    __nv_bfloat16 l1 = __float2bfloat16(v.y - __bfloat162float(h1));
    __nv_bfloat162 hh = __halves2bfloat162(h0, h1);
    __nv_bfloat162 ll = __halves2bfloat162(l0, l1);
    __nv_bfloat162* d = (__nv_bfloat162*)dst + (size_t)r * (3 * K2);
    d[cc] = hh; d[K2 + cc] = ll; d[2 * K2 + cc] = hh;
}

// ---------------- prep: X3 = [[emb||enc]h | same h | lo]; zero h0 + barrier ----
__global__ void prep_kernel(const float* __restrict__ enc,
                            const int*   __restrict__ captions,
                            const float* __restrict__ emb_table,
                            __nv_bfloat16* __restrict__ X3,
                            float* __restrict__ h0, int* __restrict__ bar)
{
    int blk = blockIdx.x;
    if (blk < MROWS) {
        int b = blk >> 6;
        int cap = captions[blk];
        const float* erow = emb_table + (size_t)cap * 512;
        const float* crow = enc + (size_t)b * 256;
        size_t base = (size_t)blk * KX3;
        for (int c = threadIdx.x; c < XD; c += 256) {
            float x = (c < 512) ? erow[c] : crow[c - 512];
            __nv_bfloat16 h = __float2bfloat16(x);
            __nv_bfloat16 l = __float2bfloat16(x - __bfloat162float(h));
            X3[base + c] = h;
            X3[base + XD + c] = h;
            X3[base + 2 * XD + c] = l;
        }
    } else {
        int i = (blk - MROWS) * 256 + threadIdx.x;   // 0..4095
        ((float4*)h0)[i] = make_float4(0.f, 0.f, 0.f, 0.f);
        if (i == 0) *bar = 0;
    }
}

// ---------------- HMMA GEMM: C[M,N] = A[M,K] B[N,K]^T + bias ------------------
// bf16 in, fp32 out. CTA 128x128, 8 warps (2m x 4n) of 64x32. K-chunk 64,
// SW128-swizzled SMEM tiles (128 rows x 128B), 3-stage cp.async pipeline.
#define KC 64
#define STAGE_BYTES 32768
#define GSMEM (3 * STAGE_BYTES)

__global__ __launch_bounds__(256, 1) void hmma_gemm(
    const __nv_bfloat16* __restrict__ A, const __nv_bfloat16* __restrict__ B,
    float* __restrict__ C,
    const float* __restrict__ bias0, const float* __restrict__ bias1,
    int M, int N, int K)
{
    extern __shared__ char smem[];
    const uint32_t sb = smem_u32(smem);
    const int tid  = threadIdx.x;
    const int lane = tid & 31, wid = tid >> 5;
    const int m0 = blockIdx.y * 128, n0 = blockIdx.x * 128;
    const int wm = wid & 1, wn = wid >> 1;
    const int nch = K / KC;

    // ldmatrix per-lane geometry (row.col NT layout, both operands K-major)
    const int rowA = wm * 64 + (lane & 7) + ((lane >> 3) & 1) * 8;
    const int kxA  = ((lane >> 4) * 16) ^ ((rowA & 7) * 16);
    const int rowB = wn * 32 + (lane & 7) + ((lane >= 16) ? 8 : 0);
    const int kxB  = (((lane >> 3) & 1) * 16) ^ ((rowB & 7) * 16);

    float acc[4][4][4];
#pragma unroll
    for (int i = 0; i < 4; i++)
#pragma unroll
        for (int j = 0; j < 4; j++)
#pragma unroll
            for (int e = 0; e < 4; e++) acc[i][j][e] = 0.f;

    // cp.async prefetch of one K-chunk into a stage
    const int prow = tid >> 3;          // base row pattern (idx = tid + j*256)
    const int pcc  = tid & 7;
#define PREFETCH(stage, kt)                                                     \
    do {                                                                        \
        uint32_t ab = sb + (stage) * STAGE_BYTES;                               \
        _Pragma("unroll")                                                       \
        for (int j = 0; j < 4; j++) {                                           \
            int row = prow + j * 32;                                            \
            uint32_t dst = ab + (uint32_t)(row * 128 + ((pcc * 16) ^ ((row & 7) * 16))); \
            cpasync16(dst, A + (size_t)(m0 + row) * K + (kt) + pcc * 8);        \
        }                                                                       \
        _Pragma("unroll")                                                       \
        for (int j = 0; j < 4; j++) {                                           \
            int row = prow + j * 32;                                            \
            int gn = n0 + row;                                                  \
            uint32_t dst = ab + 16384u + (uint32_t)(row * 128 + ((pcc * 16) ^ ((row & 7) * 16))); \
            int gnc = gn < N ? gn : N - 1;                                      \
            cpasync16z(dst, B + (size_t)gnc * K + (kt) + pcc * 8,               \
                       gn < N ? 16u : 0u);                                      \
        }                                                                       \
        CP_COMMIT();                                                            \
    } while (0)

    PREFETCH(0, 0);
    PREFETCH(1, KC);

    for (int c = 0; c < nch; c++) {
        if (c + 2 < nch) PREFETCH((c + 2) % 3, (c + 2) * KC);
        if (c + 2 < nch)      asm volatile("cp.async.wait_group 2;" ::: "memory");
        else if (c + 1 < nch) asm volatile("cp.async.wait_group 1;" ::: "memory");
        else                  asm volatile("cp.async.wait_group 0;" ::: "memory");
        __syncthreads();

        const uint32_t As = sb + (c % 3) * STAGE_BYTES;
        const uint32_t Bs = As + 16384;
#pragma unroll
        for (int ks = 0; ks < 4; ks++) {
            uint32_t a[4][4], b[2][4];
#pragma unroll
            for (int mt = 0; mt < 4; mt++)
                ldsm4(a[mt], As + (uint32_t)((rowA + mt * 16) * 128 + ((ks * 32) ^ kxA)));
#pragma unroll
            for (int nt2 = 0; nt2 < 2; nt2++)
                ldsm4(b[nt2], Bs + (uint32_t)((rowB + nt2 * 16) * 128 + ((ks * 32) ^ kxB)));
#pragma unroll
            for (int mt = 0; mt < 4; mt++)
#pragma unroll
                for (int nt = 0; nt < 4; nt++)
                    mma16816(acc[mt][nt], a[mt],
                             b[nt >> 1][(nt & 1) * 2], b[nt >> 1][(nt & 1) * 2 + 1]);
        }
        __syncthreads();
    }

    // epilogue
    const int mrow  = m0 + wm * 64 + (lane >> 2);
    const int ncol0 = n0 + wn * 32 + (lane & 3) * 2;
#pragma unroll
    for (int mt = 0; mt < 4; mt++) {
#pragma unroll
        for (int nt = 0; nt < 4; nt++) {
            int cc = ncol0 + nt * 8;
            if (cc < N) {
                float b0v = bias0[cc], b1v = bias0[cc + 1];
                if (bias1) { b0v += bias1[cc]; b1v += bias1[cc + 1]; }
                int r0 = mrow + mt * 16;
                float2 v0 = make_float2(acc[mt][nt][0] + b0v, acc[mt][nt][1] + b1v);
                float2 v1 = make_float2(acc[mt][nt][2] + b0v, acc[mt][nt][3] + b1v);
                *(float2*)(C + (size_t)r0 * N + cc)       = v0;
                *(float2*)(C + (size_t)(r0 + 8) * N + cc) = v1;
            }
        }
    }
#undef PREFETCH
}

// ---------------- persistent LSTM over all 64 steps ---------------------------
// 128 CTAs x 128 threads. CTA owns 4 hidden units (16 gate rows in SMEM),
// c resident in SMEM, h exchanged via L2 (__ldcg) + monotonic grid barrier.
// Pointwise epilogue also emits H3 = [Hh|Hh|Hl] bf16 rows for the final GEMM.
__device__ __forceinline__ float sigf(float x) { return 1.0f / (1.0f + expf(-x)); }
#define WSP 520
#define LSM_BYTES ((16 * WSP + 512 * 32 + 16 * 32 + 128) * 4)

__global__ __launch_bounds__(128, 1) void lstm_persistent(
    const float* __restrict__ pregates,
    const float* __restrict__ W_hh,
    float* __restrict__ hA, float* __restrict__ hB,
    __nv_bfloat16* __restrict__ H3, int* __restrict__ bar)
{
    extern __shared__ float sm[];
    float* Ws  = sm;                        // 16 x WSP
    float* hs  = sm + 16 * WSP;             // 512 x 32
    float* gsm = hs + 512 * 32;             // 16 x 32
    float* csm = gsm + 512;                 // 128

    const int tid = threadIdx.x;
    const int nb  = blockIdx.x * 4;

    // stage 16 gate rows of W_hh (row rr -> gate rr>>2, unit nb + (rr&3))
    for (int i = tid; i < 2048; i += 128) {
        int rr = i >> 7, kq = (i & 127) * 4;
        int gate = rr >> 2, nl = rr & 3;
        *(float4*)&Ws[rr * WSP + kq] =
            *(const float4*)&W_hh[((size_t)(gate * HID + nb + nl)) * HID + kq];
    }
    csm[tid] = 0.0f;
    __syncthreads();

    const int r  = tid >> 3;          // gate row 0..15
    const int b0 = (tid & 7) * 4;     // batch quad
    const float* wr = Ws + r * WSP;

    for (int t = 0; t < TT; t++) {
        const float* hin = (t & 1) ? hB : hA;
        for (int i = tid; i < 4096; i += 128)
            *(float4*)&hs[i * 4] = __ldcg(((const float4*)hin) + i);
        __syncthreads();

        float a0 = 0.f, a1 = 0.f, a2 = 0.f, a3 = 0.f;
#pragma unroll 2
        for (int k = 0; k < 512; k += 4) {
            float4 w  = *(const float4*)&wr[k];
            float4 h0 = *(const float4*)&hs[(k + 0) * 32 + b0];
            float4 h1 = *(const float4*)&hs[(k + 1) * 32 + b0];
            float4 h2 = *(const float4*)&hs[(k + 2) * 32 + b0];
            float4 h3 = *(const float4*)&hs[(k + 3) * 32 + b0];
            a0 = fmaf(w.x, h0.x, a0); a1 = fmaf(w.x, h0.y, a1);
            a2 = fmaf(w.x, h0.z, a2); a3 = fmaf(w.x, h0.w, a3);
            a0 = fmaf(w.y, h1.x, a0); a1 = fmaf(w.y, h1.y, a1);
            a2 = fmaf(w.y, h1.z, a2); a3 = fmaf(w.y, h1.w, a3);
            a0 = fmaf(w.z, h2.x, a0); a1 = fmaf(w.z, h2.y, a1);
            a2 = fmaf(w.z, h2.z, a2); a3 = fmaf(w.z, h2.w, a3);
            a0 = fmaf(w.w, h3.x, a0); a1 = fmaf(w.w, h3.y, a1);
            a2 = fmaf(w.w, h3.z, a2); a3 = fmaf(w.w, h3.w, a3);
        }
        *(float4*)&gsm[r * 32 + b0] = make_float4(a0, a1, a2, a3);
        __syncthreads();

        {   // pointwise: 128 threads = 32 b x 4 units
            int b = tid >> 2, nl = tid & 3;
            int n = nb + nl;
            size_t pg = ((size_t)b * TT + t) * G4 + n;
            float gi = gsm[(0  + nl) * 32 + b] + pregates[pg];
            float gf = gsm[(4  + nl) * 32 + b] + pregates[pg + 512];
            float gg = gsm[(8  + nl) * 32 + b] + pregates[pg + 1024];
            float go = gsm[(12 + nl) * 32 + b] + pregates[pg + 1536];
            float c_old = csm[tid];
            float cn = sigf(gf) * c_old + sigf(gi) * tanhf(gg);
            float hn = sigf(go) * tanhf(cn);
            csm[tid] = cn;
            float* hout = (t & 1) ? hA : hB;
            hout[n * 32 + b] = hn;
            __nv_bfloat16 hh = __float2bfloat16(hn);
            __nv_bfloat16 hl = __float2bfloat16(hn - __bfloat162float(hh));
            size_t hb = ((size_t)b * TT + t) * KH3;
            H3[hb + n] = hh; H3[hb + 512 + n] = hh; H3[hb + 1024 + n] = hl;
        }

        if (t < TT - 1) {
            __threadfence();
            __syncthreads();
            if (tid == 0) {
                atomicAdd(bar, 1);
                int target = 128 * (t + 1);
                while (*((volatile int*)bar) < target) { }
            }
            __syncthreads();
            __threadfence();
        }
    }
}

// ---------------- launch ------------------------------------------------------
extern "C" void kernel_launch(void* const* d_in, const int* in_sizes, int n_in,
                              void* d_out, int out_size)
{
    const float* enc       = (const float*)d_in[0];
    const int*   captions  = (const int*)  d_in[1];
    const float* emb_table = (const float*)d_in[8];
    const float* W_ih      = (const float*)d_in[9];
    const float* W_hh      = (const float*)d_in[10];
    const float* b_ih      = (const float*)d_in[11];
    const float* b_hh      = (const float*)d_in[12];
    const float* W_fc      = (const float*)d_in[13];
    const float* b_fc      = (const float*)d_in[14];
    float* out = (float*)d_out;

    __nv_bfloat16 *pX3, *pWih3, *pWfc3, *pH3;
    float *pPG, *phA, *phB;
    int* pBar;
    cudaGetSymbolAddress((void**)&pX3, g_X3);
    cudaGetSymbolAddress((void**)&pWih3, g_Wih3);
    cudaGetSymbolAddress((void**)&pWfc3, g_Wfc3);
    cudaGetSymbolAddress((void**)&pH3, g_H3);
    cudaGetSymbolAddress((void**)&pPG, g_pg);
    cudaGetSymbolAddress((void**)&phA, g_hA);
    cudaGetSymbolAddress((void**)&phB, g_hB);
    cudaGetSymbolAddress((void**)&pBar, g_bar);

    cudaFuncSetAttribute(hmma_gemm, cudaFuncAttributeMaxDynamicSharedMemorySize, GSMEM);
    cudaFuncSetAttribute(lstm_persistent, cudaFuncAttributeMaxDynamicSharedMemorySize, LSM_BYTES);

    // 1) weight splits -> [h|l|h] concatenated bf16
    split3b_kernel<<<(G4 * XD / 2 + 255) / 256, 256>>>(W_ih, pWih3, XD / 2, G4 * XD / 2);
    split3b_kernel<<<(VV * HID / 2 + 255) / 256, 256>>>(W_fc, pWfc3, HID / 2, VV * HID / 2);

    // 2) build X3, zero h0 + barrier
    prep_kernel<<<MROWS + 16, 256>>>(enc, captions, emb_table, pX3, phA, pBar);

    // 3) pregates = X @ W_ih^T + b_ih + b_hh   (K' = 2304)
    {
        dim3 grid(G4 / 128, MROWS / 128);
        hmma_gemm<<<grid, 256, GSMEM>>>(pX3, pWih3, pPG, b_ih, b_hh,
                                        MROWS, G4, KX3);
    }

    // 4) persistent LSTM (one launch, emits H3 inline)
    lstm_persistent<<<128, 128, LSM_BYTES>>>(pPG, W_hh, phA, phB, pH3, pBar);

    // 5) out = H @ W_fc^T + b_fc   (K' = 1536)
    {
        dim3 grid((VV + 127) / 128, MROWS / 128);
        hmma_gemm<<<grid, 256, GSMEM>>>(pH3, pWfc3, out, b_fc, nullptr,
                                        MROWS, VV, KH3);
    }
}

// round 4
// speedup vs baseline: 2.2648x; 1.1170x over previous
#include <cuda_runtime.h>
#include <cuda_bf16.h>
#include <math.h>
#include <stdint.h>

// Problem dims
#define TT   64
#define VV   30000
#define HID  512
#define XD   768          // EMB + E
#define G4   2048         // 4*H
#define MROWS 2048        // B*T
#define KX3  (3 * XD)     // 2304
#define KH3  (3 * HID)    // 1536

// ---------------- scratch (device globals; no allocation allowed) -------------
__device__ __align__(16) __nv_bfloat16 g_X3  [MROWS * KX3];   // [Xh|Xh|Xl]
__device__ __align__(16) __nv_bfloat16 g_Wih3[G4 * KX3];      // [Wh|Wl|Wh]
__device__ __align__(16) __nv_bfloat16 g_Wfc3[(size_t)VV * KH3]; // [Wh|Wl|Wh]
__device__ __align__(16) __nv_bfloat16 g_H3  [MROWS * KH3];   // [Hh|Hh|Hl]
__device__ __align__(16) float g_pg[MROWS * G4];
__device__ __align__(16) float g_hA[HID * 32];
__device__ __align__(16) float g_hB[HID * 32];
__device__ int g_bar;

// ---------------- small helpers ------------------------------------------------
__device__ __forceinline__ uint32_t smem_u32(const void* p) {
    uint32_t a;
    asm("{ .reg .u64 t; cvta.to.shared.u64 t, %1; cvt.u32.u64 %0, t; }" : "=r"(a) : "l"(p));
    return a;
}
__device__ __forceinline__ void ldsm4(uint32_t* r, uint32_t addr) {
    asm volatile("ldmatrix.sync.aligned.m8n8.x4.shared.b16 {%0,%1,%2,%3}, [%4];"
                 : "=r"(r[0]), "=r"(r[1]), "=r"(r[2]), "=r"(r[3]) : "r"(addr));
}
__device__ __forceinline__ void mma16816(float* d, const uint32_t* a,
                                         uint32_t b0, uint32_t b1) {
    asm volatile("mma.sync.aligned.m16n8k16.row.col.f32.bf16.bf16.f32 "
                 "{%0,%1,%2,%3}, {%4,%5,%6,%7}, {%8,%9}, {%0,%1,%2,%3};"
                 : "+f"(d[0]), "+f"(d[1]), "+f"(d[2]), "+f"(d[3])
                 : "r"(a[0]), "r"(a[1]), "r"(a[2]), "r"(a[3]), "r"(b0), "r"(b1));
}
__device__ __forceinline__ void cpasync16(uint32_t dst, const void* src) {
    asm volatile("cp.async.cg.shared.global [%0], [%1], 16;" :: "r"(dst), "l"(src));
}
__device__ __forceinline__ void cpasync16z(uint32_t dst, const void* src, unsigned sz) {
    asm volatile("cp.async.cg.shared.global [%0], [%1], 16, %2;"
                 :: "r"(dst), "l"(src), "r"(sz));
}
#define CP_COMMIT() asm volatile("cp.async.commit_group;" ::: "memory")

// ---------------- split weights: src fp32 [R,K] -> dst bf16 [R,3K] = [h|l|h] ---
__global__ void split3b_kernel(const float* __restrict__ src,
                               __nv_bfloat16* __restrict__ dst,
                               int K2, int total2)   // K2 = K/2
{
    int i = blockIdx.x * 256 + threadIdx.x;
    if (i >= total2) return;
    int r = i / K2, cc = i - r * K2;
    float2 v = ((const float2*)src)[i];
    __nv_bfloat16 h0 = __float2bfloat16(v.x), h1 = __float2bfloat16(v.y);
    __nv_bfloat16 l0 = __float2bfloat16(v.x - __bfloat162float(h0));
    __nv_bfloat16 l1 = __float2bfloat16(v.y - __bfloat162float(h1));
    __nv_bfloat162 hh = __halves2bfloat162(h0, h1);
    __nv_bfloat162 ll = __halves2bfloat162(l0, l1);
    __nv_bfloat162* d = (__nv_bfloat162*)dst + (size_t)r * (3 * K2);
    d[cc] = hh; d[K2 + cc] = ll; d[2 * K2 + cc] = hh;
}

// ---------------- prep: X3 = [[emb||enc]h | same h | lo]; zero h0 + barrier ----
__global__ void prep_kernel(const float* __restrict__ enc,
                            const int*   __restrict__ captions,
                            const float* __restrict__ emb_table,
                            __nv_bfloat16* __restrict__ X3,
                            float* __restrict__ h0, int* __restrict__ bar)
{
    int blk = blockIdx.x;
    if (blk < MROWS) {
        int b = blk >> 6;
        int cap = captions[blk];
        const float* erow = emb_table + (size_t)cap * 512;
        const float* crow = enc + (size_t)b * 256;
        size_t base = (size_t)blk * KX3;
        for (int c = threadIdx.x; c < XD; c += 256) {
            float x = (c < 512) ? erow[c] : crow[c - 512];
            __nv_bfloat16 h = __float2bfloat16(x);
            __nv_bfloat16 l = __float2bfloat16(x - __bfloat162float(h));
            X3[base + c] = h;
            X3[base + XD + c] = h;
            X3[base + 2 * XD + c] = l;
        }
    } else {
        int i = (blk - MROWS) * 256 + threadIdx.x;   // 0..4095
        ((float4*)h0)[i] = make_float4(0.f, 0.f, 0.f, 0.f);
        if (i == 0) *bar = 0;
    }
}

// ---------------- HMMA GEMM: C[M,N] = A[M,K] B[N,K]^T + bias ------------------
// bf16 in, fp32 out. CTA 128x128, 8 warps (2m x 4n) of 64x32. K-chunk 64,
// SW128-swizzled SMEM tiles (128 rows x 128B), 3-stage cp.async pipeline.
// launch_bounds(256,2): cap regs at 128 so 2 CTAs co-reside per SM (16 warps)
// -> barrier/ldsm/cp.async latency absorbed by the sibling CTA.
#define KC 64
#define STAGE_BYTES 32768
#define GSMEM (3 * STAGE_BYTES)

__global__ __launch_bounds__(256, 2) void hmma_gemm(
    const __nv_bfloat16* __restrict__ A, const __nv_bfloat16* __restrict__ B,
    float* __restrict__ C,
    const float* __restrict__ bias0, const float* __restrict__ bias1,
    int M, int N, int K)
{
    extern __shared__ char smem[];
    const uint32_t sb = smem_u32(smem);
    const int tid  = threadIdx.x;
    const int lane = tid & 31, wid = tid >> 5;
    const int m0 = blockIdx.y * 128, n0 = blockIdx.x * 128;
    const int wm = wid & 1, wn = wid >> 1;
    const int nch = K / KC;

    // ldmatrix per-lane geometry (row.col NT layout, both operands K-major)
    const int rowA = wm * 64 + (lane & 7) + ((lane >> 3) & 1) * 8;
    const int kxA  = ((lane >> 4) * 16) ^ ((rowA & 7) * 16);
    const int rowB = wn * 32 + (lane & 7) + ((lane >= 16) ? 8 : 0);
    const int kxB  = (((lane >> 3) & 1) * 16) ^ ((rowB & 7) * 16);

    float acc[4][4][4];
#pragma unroll
    for (int i = 0; i < 4; i++)
#pragma unroll
        for (int j = 0; j < 4; j++)
#pragma unroll
            for (int e = 0; e < 4; e++) acc[i][j][e] = 0.f;

    // cp.async prefetch of one K-chunk into a stage
    const int prow = tid >> 3;          // base row pattern (idx = tid + j*256)
    const int pcc  = tid & 7;
#define PREFETCH(stage, kt)                                                     \
    do {                                                                        \
        uint32_t ab = sb + (stage) * STAGE_BYTES;                               \
        _Pragma("unroll")                                                       \
        for (int j = 0; j < 4; j++) {                                           \
            int row = prow + j * 32;                                            \
            uint32_t dst = ab + (uint32_t)(row * 128 + ((pcc * 16) ^ ((row & 7) * 16))); \
            cpasync16(dst, A + (size_t)(m0 + row) * K + (kt) + pcc * 8);        \
        }                                                                       \
        _Pragma("unroll")                                                       \
        for (int j = 0; j < 4; j++) {                                           \
            int row = prow + j * 32;                                            \
            int gn = n0 + row;                                                  \
            uint32_t dst = ab + 16384u + (uint32_t)(row * 128 + ((pcc * 16) ^ ((row & 7) * 16))); \
            int gnc = gn < N ? gn : N - 1;                                      \
            cpasync16z(dst, B + (size_t)gnc * K + (kt) + pcc * 8,               \
                       gn < N ? 16u : 0u);                                      \
        }                                                                       \
        CP_COMMIT();                                                            \
    } while (0)

    PREFETCH(0, 0);
    PREFETCH(1, KC);

    for (int c = 0; c < nch; c++) {
        if (c + 2 < nch) PREFETCH((c + 2) % 3, (c + 2) * KC);
        if (c + 2 < nch)      asm volatile("cp.async.wait_group 2;" ::: "memory");
        else if (c + 1 < nch) asm volatile("cp.async.wait_group 1;" ::: "memory");
        else                  asm volatile("cp.async.wait_group 0;" ::: "memory");
        __syncthreads();

        const uint32_t As = sb + (c % 3) * STAGE_BYTES;
        const uint32_t Bs = As + 16384;
#pragma unroll
        for (int ks = 0; ks < 4; ks++) {
            uint32_t a[4][4], b[2][4];
#pragma unroll
            for (int mt = 0; mt < 4; mt++)
                ldsm4(a[mt], As + (uint32_t)((rowA + mt * 16) * 128 + ((ks * 32) ^ kxA)));
#pragma unroll
            for (int nt2 = 0; nt2 < 2; nt2++)
                ldsm4(b[nt2], Bs + (uint32_t)((rowB + nt2 * 16) * 128 + ((ks * 32) ^ kxB)));
#pragma unroll
            for (int mt = 0; mt < 4; mt++)
#pragma unroll
                for (int nt = 0; nt < 4; nt++)
                    mma16816(acc[mt][nt], a[mt],
                             b[nt >> 1][(nt & 1) * 2], b[nt >> 1][(nt & 1) * 2 + 1]);
        }
        __syncthreads();
    }

    // epilogue
    const int mrow  = m0 + wm * 64 + (lane >> 2);
    const int ncol0 = n0 + wn * 32 + (lane & 3) * 2;
#pragma unroll
    for (int mt = 0; mt < 4; mt++) {
#pragma unroll
        for (int nt = 0; nt < 4; nt++) {
            int cc = ncol0 + nt * 8;
            if (cc < N) {
                float b0v = bias0[cc], b1v = bias0[cc + 1];
                if (bias1) { b0v += bias1[cc]; b1v += bias1[cc + 1]; }
                int r0 = mrow + mt * 16;
                float2 v0 = make_float2(acc[mt][nt][0] + b0v, acc[mt][nt][1] + b1v);
                float2 v1 = make_float2(acc[mt][nt][2] + b0v, acc[mt][nt][3] + b1v);
                *(float2*)(C + (size_t)r0 * N + cc)       = v0;
                *(float2*)(C + (size_t)(r0 + 8) * N + cc) = v1;
            }
        }
    }
#undef PREFETCH
}

// ---------------- persistent LSTM over all 64 steps ---------------------------
// 128 CTAs x 128 threads. CTA owns 4 hidden units (16 gate rows in SMEM),
// c resident in SMEM, h exchanged via L2 (__ldcg) + monotonic grid barrier.
// Pointwise epilogue also emits H3 = [Hh|Hh|Hl] bf16 rows for the final GEMM.
__device__ __forceinline__ float sigf(float x) { return 1.0f / (1.0f + expf(-x)); }
#define WSP 520
#define LSM_BYTES ((16 * WSP + 512 * 32 + 16 * 32 + 128) * 4)

__global__ __launch_bounds__(128, 1) void lstm_persistent(
    const float* __restrict__ pregates,
    const float* __restrict__ W_hh,
    float* __restrict__ hA, float* __restrict__ hB,
    __nv_bfloat16* __restrict__ H3, int* __restrict__ bar)
{
    extern __shared__ float sm[];
    float* Ws  = sm;                        // 16 x WSP
    float* hs  = sm + 16 * WSP;             // 512 x 32
    float* gsm = hs + 512 * 32;             // 16 x 32
    float* csm = gsm + 512;                 // 128

    const int tid = threadIdx.x;
    const int nb  = blockIdx.x * 4;

    // stage 16 gate rows of W_hh (row rr -> gate rr>>2, unit nb + (rr&3))
    for (int i = tid; i < 2048; i += 128) {
        int rr = i >> 7, kq = (i & 127) * 4;
        int gate = rr >> 2, nl = rr & 3;
        *(float4*)&Ws[rr * WSP + kq] =
            *(const float4*)&W_hh[((size_t)(gate * HID + nb + nl)) * HID + kq];
    }
    csm[tid] = 0.0f;
    __syncthreads();

    const int r  = tid >> 3;          // gate row 0..15
    const int b0 = (tid & 7) * 4;     // batch quad
    const float* wr = Ws + r * WSP;

    for (int t = 0; t < TT; t++) {
        const float* hin = (t & 1) ? hB : hA;
        for (int i = tid; i < 4096; i += 128)
            *(float4*)&hs[i * 4] = __ldcg(((const float4*)hin) + i);
        __syncthreads();

        float a0 = 0.f, a1 = 0.f, a2 = 0.f, a3 = 0.f;
#pragma unroll 2
        for (int k = 0; k < 512; k += 4) {
            float4 w  = *(const float4*)&wr[k];
            float4 h0 = *(const float4*)&hs[(k + 0) * 32 + b0];
            float4 h1 = *(const float4*)&hs[(k + 1) * 32 + b0];
            float4 h2 = *(const float4*)&hs[(k + 2) * 32 + b0];
            float4 h3 = *(const float4*)&hs[(k + 3) * 32 + b0];
            a0 = fmaf(w.x, h0.x, a0); a1 = fmaf(w.x, h0.y, a1);
            a2 = fmaf(w.x, h0.z, a2); a3 = fmaf(w.x, h0.w, a3);
            a0 = fmaf(w.y, h1.x, a0); a1 = fmaf(w.y, h1.y, a1);
            a2 = fmaf(w.y, h1.z, a2); a3 = fmaf(w.y, h1.w, a3);
            a0 = fmaf(w.z, h2.x, a0); a1 = fmaf(w.z, h2.y, a1);
            a2 = fmaf(w.z, h2.z, a2); a3 = fmaf(w.z, h2.w, a3);
            a0 = fmaf(w.w, h3.x, a0); a1 = fmaf(w.w, h3.y, a1);
            a2 = fmaf(w.w, h3.z, a2); a3 = fmaf(w.w, h3.w, a3);
        }
        *(float4*)&gsm[r * 32 + b0] = make_float4(a0, a1, a2, a3);
        __syncthreads();

        {   // pointwise: 128 threads = 32 b x 4 units
            int b = tid >> 2, nl = tid & 3;
            int n = nb + nl;
            size_t pg = ((size_t)b * TT + t) * G4 + n;
            float gi = gsm[(0  + nl) * 32 + b] + pregates[pg];
            float gf = gsm[(4  + nl) * 32 + b] + pregates[pg + 512];
            float gg = gsm[(8  + nl) * 32 + b] + pregates[pg + 1024];
            float go = gsm[(12 + nl) * 32 + b] + pregates[pg + 1536];
            float c_old = csm[tid];
            float cn = sigf(gf) * c_old + sigf(gi) * tanhf(gg);
            float hn = sigf(go) * tanhf(cn);
            csm[tid] = cn;
            float* hout = (t & 1) ? hA : hB;
            hout[n * 32 + b] = hn;
            __nv_bfloat16 hh = __float2bfloat16(hn);
            __nv_bfloat16 hl = __float2bfloat16(hn - __bfloat162float(hh));
            size_t hb = ((size_t)b * TT + t) * KH3;
            H3[hb + n] = hh; H3[hb + 512 + n] = hh; H3[hb + 1024 + n] = hl;
        }

        if (t < TT - 1) {
            __threadfence();
            __syncthreads();
            if (tid == 0) {
                atomicAdd(bar, 1);
                int target = 128 * (t + 1);
                while (*((volatile int*)bar) < target) { }
            }
            __syncthreads();
            __threadfence();
        }
    }
}

// ---------------- launch ------------------------------------------------------
extern "C" void kernel_launch(void* const* d_in, const int* in_sizes, int n_in,
                              void* d_out, int out_size)
{
    const float* enc       = (const float*)d_in[0];
    const int*   captions  = (const int*)  d_in[1];
    const float* emb_table = (const float*)d_in[8];
    const float* W_ih      = (const float*)d_in[9];
    const float* W_hh      = (const float*)d_in[10];
    const float* b_ih      = (const float*)d_in[11];
    const float* b_hh      = (const float*)d_in[12];
    const float* W_fc      = (const float*)d_in[13];
    const float* b_fc      = (const float*)d_in[14];
    float* out = (float*)d_out;

    __nv_bfloat16 *pX3, *pWih3, *pWfc3, *pH3;
    float *pPG, *phA, *phB;
    int* pBar;
    cudaGetSymbolAddress((void**)&pX3, g_X3);
    cudaGetSymbolAddress((void**)&pWih3, g_Wih3);
    cudaGetSymbolAddress((void**)&pWfc3, g_Wfc3);
    cudaGetSymbolAddress((void**)&pH3, g_H3);
    cudaGetSymbolAddress((void**)&pPG, g_pg);
    cudaGetSymbolAddress((void**)&phA, g_hA);
    cudaGetSymbolAddress((void**)&phB, g_hB);
    cudaGetSymbolAddress((void**)&pBar, g_bar);

    cudaFuncSetAttribute(hmma_gemm, cudaFuncAttributeMaxDynamicSharedMemorySize, GSMEM);
    cudaFuncSetAttribute(lstm_persistent, cudaFuncAttributeMaxDynamicSharedMemorySize, LSM_BYTES);

    // 1) weight splits -> [h|l|h] concatenated bf16
    split3b_kernel<<<(G4 * XD / 2 + 255) / 256, 256>>>(W_ih, pWih3, XD / 2, G4 * XD / 2);
    split3b_kernel<<<(VV * HID / 2 + 255) / 256, 256>>>(W_fc, pWfc3, HID / 2, VV * HID / 2);

    // 2) build X3, zero h0 + barrier
    prep_kernel<<<MROWS + 16, 256>>>(enc, captions, emb_table, pX3, phA, pBar);

    // 3) pregates = X @ W_ih^T + b_ih + b_hh   (K' = 2304)
    {
        dim3 grid(G4 / 128, MROWS / 128);
        hmma_gemm<<<grid, 256, GSMEM>>>(pX3, pWih3, pPG, b_ih, b_hh,
                                        MROWS, G4, KX3);
    }

    // 4) persistent LSTM (one launch, emits H3 inline)
    lstm_persistent<<<128, 128, LSM_BYTES>>>(pPG, W_hh, phA, phB, pH3, pBar);

    // 5) out = H @ W_fc^T + b_fc   (K' = 1536)
    {
        dim3 grid((VV + 127) / 128, MROWS / 128);
        hmma_gemm<<<grid, 256, GSMEM>>>(pH3, pWfc3, out, b_fc, nullptr,
                                        MROWS, VV, KH3);
    }
}

// round 6
// speedup vs baseline: 5.5284x; 2.4410x over previous
#include <cuda_runtime.h>
#include <cuda_fp16.h>
#include <math.h>
#include <stdint.h>

// Problem dims
#define TT   64
#define VV   30000
#define HID  512
#define XD   768          // EMB + E
#define G4   2048         // 4*H
#define MROWS 2048        // B*T

// ---------------- scratch (device globals; no allocation allowed) -------------
__device__ __align__(16) __half g_X2  [MROWS * XD];          // fp16 X
__device__ __align__(16) __half g_Wih2[G4 * XD];             // fp16 W_ih
__device__ __align__(16) __half g_Whh2[G4 * HID];            // fp16 W_hh
__device__ __align__(16) __half g_Wfc2[(size_t)VV * HID];    // fp16 W_fc
__device__ __align__(16) __half g_H2  [MROWS * HID];         // fp16 hidden history
__device__ __align__(16) __half g_h2A [32 * HID];            // h state ping
__device__ __align__(16) __half g_h2B [32 * HID];            // h state pong
__device__ __align__(16) float  g_pg[MROWS * G4];            // pregates fp32
__device__ int g_bar;

// ---------------- small helpers ------------------------------------------------
__device__ __forceinline__ uint32_t smem_u32(const void* p) {
    uint32_t a;
    asm("{ .reg .u64 t; cvta.to.shared.u64 t, %1; cvt.u32.u64 %0, t; }" : "=r"(a) : "l"(p));
    return a;
}
__device__ __forceinline__ void ldsm4(uint32_t* r, uint32_t addr) {
    asm volatile("ldmatrix.sync.aligned.m8n8.x4.shared.b16 {%0,%1,%2,%3}, [%4];"
                 : "=r"(r[0]), "=r"(r[1]), "=r"(r[2]), "=r"(r[3]) : "r"(addr));
}
__device__ __forceinline__ void mma16816(float* d, const uint32_t* a,
                                         uint32_t b0, uint32_t b1) {
    asm volatile("mma.sync.aligned.m16n8k16.row.col.f32.f16.f16.f32 "
                 "{%0,%1,%2,%3}, {%4,%5,%6,%7}, {%8,%9}, {%0,%1,%2,%3};"
                 : "+f"(d[0]), "+f"(d[1]), "+f"(d[2]), "+f"(d[3])
                 : "r"(a[0]), "r"(a[1]), "r"(a[2]), "r"(a[3]), "r"(b0), "r"(b1));
}
__device__ __forceinline__ void cpasync16(uint32_t dst, const void* src) {
    asm volatile("cp.async.cg.shared.global [%0], [%1], 16;" :: "r"(dst), "l"(src));
}
__device__ __forceinline__ void cpasync16z(uint32_t dst, const void* src, unsigned sz) {
    asm volatile("cp.async.cg.shared.global [%0], [%1], 16, %2;"
                 :: "r"(dst), "l"(src), "r"(sz));
}
#define CP_COMMIT() asm volatile("cp.async.commit_group;" ::: "memory")
#define CP_WAIT0()  asm volatile("cp.async.wait_group 0;" ::: "memory")

// ---------------- fp32 -> fp16 convert ----------------------------------------
__global__ void cvt2h_kernel(const float* __restrict__ src,
                             __half* __restrict__ dst, int n2)
{
    int i = blockIdx.x * 256 + threadIdx.x;
    if (i >= n2) return;
    float2 v = ((const float2*)src)[i];
    ((__half2*)dst)[i] = __floats2half2_rn(v.x, v.y);
}

// ---------------- prep: X2 = fp16([emb||enc]); zero FULL h ping + barrier ------
__global__ void prep_kernel(const float* __restrict__ enc,
                            const int*   __restrict__ captions,
                            const float* __restrict__ emb_table,
                            __half* __restrict__ X2,
                            __half* __restrict__ h0, int* __restrict__ bar)
{
    int blk = blockIdx.x;
    if (blk < MROWS) {
        int b = blk >> 6;
        int cap = captions[blk];
        const float* erow = emb_table + (size_t)cap * 512;
        const float* crow = enc + (size_t)b * 256;
        size_t base = (size_t)blk * XD;
        for (int c = threadIdx.x; c < XD; c += 256) {
            float x = (c < 512) ? erow[c] : crow[c - 512];
            X2[base + c] = __float2half(x);
        }
    } else {
        // h0 = 32*512 halves = 8192 uint32; 32 blocks x 256 threads cover all.
        int i = (blk - MROWS) * 256 + threadIdx.x;   // 0..8191
        ((uint32_t*)h0)[i] = 0u;
        if (i == 0) *bar = 0;
    }
}

// ---------------- HMMA GEMM: C[M,N] = A[M,K] B[N,K]^T + bias ------------------
// fp16 in, fp32 out. CTA 128x128, 8 warps (2m x 4n) of 64x32. K-chunk 64,
// swizzled SMEM tiles (128 rows x 128B), 3-stage cp.async pipeline, 2 CTA/SM.
#define KC 64
#define STAGE_BYTES 32768
#define GSMEM (3 * STAGE_BYTES)

__global__ __launch_bounds__(256, 2) void hmma_gemm(
    const __half* __restrict__ A, const __half* __restrict__ B,
    float* __restrict__ C,
    const float* __restrict__ bias0, const float* __restrict__ bias1,
    int M, int N, int K)
{
    extern __shared__ char smem[];
    const uint32_t sb = smem_u32(smem);
    const int tid  = threadIdx.x;
    const int lane = tid & 31, wid = tid >> 5;
    const int m0 = blockIdx.y * 128, n0 = blockIdx.x * 128;
    const int wm = wid & 1, wn = wid >> 1;
    const int nch = K / KC;

    const int rowA = wm * 64 + (lane & 7) + ((lane >> 3) & 1) * 8;
    const int kxA  = ((lane >> 4) * 16) ^ ((rowA & 7) * 16);
    const int rowB = wn * 32 + (lane & 7) + ((lane >= 16) ? 8 : 0);
    const int kxB  = (((lane >> 3) & 1) * 16) ^ ((rowB & 7) * 16);

    float acc[4][4][4];
#pragma unroll
    for (int i = 0; i < 4; i++)
#pragma unroll
        for (int j = 0; j < 4; j++)
#pragma unroll
            for (int e = 0; e < 4; e++) acc[i][j][e] = 0.f;

    const int prow = tid >> 3;
    const int pcc  = tid & 7;
#define PREFETCH(stage, kt)                                                     \
    do {                                                                        \
        uint32_t ab = sb + (stage) * STAGE_BYTES;                               \
        _Pragma("unroll")                                                       \
        for (int j = 0; j < 4; j++) {                                           \
            int row = prow + j * 32;                                            \
            uint32_t dst = ab + (uint32_t)(row * 128 + ((pcc * 16) ^ ((row & 7) * 16))); \
            cpasync16(dst, A + (size_t)(m0 + row) * K + (kt) + pcc * 8);        \
        }                                                                       \
        _Pragma("unroll")                                                       \
        for (int j = 0; j < 4; j++) {                                           \
            int row = prow + j * 32;                                            \
            int gn = n0 + row;                                                  \
            uint32_t dst = ab + 16384u + (uint32_t)(row * 128 + ((pcc * 16) ^ ((row & 7) * 16))); \
            int gnc = gn < N ? gn : N - 1;                                      \
            cpasync16z(dst, B + (size_t)gnc * K + (kt) + pcc * 8,               \
                       gn < N ? 16u : 0u);                                      \
        }                                                                       \
        CP_COMMIT();                                                            \
    } while (0)

    PREFETCH(0, 0);
    PREFETCH(1, KC);

    for (int c = 0; c < nch; c++) {
        if (c + 2 < nch) PREFETCH((c + 2) % 3, (c + 2) * KC);
        if (c + 2 < nch)      asm volatile("cp.async.wait_group 2;" ::: "memory");
        else if (c + 1 < nch) asm volatile("cp.async.wait_group 1;" ::: "memory");
        else                  asm volatile("cp.async.wait_group 0;" ::: "memory");
        __syncthreads();

        const uint32_t As = sb + (c % 3) * STAGE_BYTES;
        const uint32_t Bs = As + 16384;
#pragma unroll
        for (int ks = 0; ks < 4; ks++) {
            uint32_t a[4][4], b[2][4];
#pragma unroll
            for (int mt = 0; mt < 4; mt++)
                ldsm4(a[mt], As + (uint32_t)((rowA + mt * 16) * 128 + ((ks * 32) ^ kxA)));
#pragma unroll
            for (int nt2 = 0; nt2 < 2; nt2++)
                ldsm4(b[nt2], Bs + (uint32_t)((rowB + nt2 * 16) * 128 + ((ks * 32) ^ kxB)));
#pragma unroll
            for (int mt = 0; mt < 4; mt++)
#pragma unroll
                for (int nt = 0; nt < 4; nt++)
                    mma16816(acc[mt][nt], a[mt],
                             b[nt >> 1][(nt & 1) * 2], b[nt >> 1][(nt & 1) * 2 + 1]);
        }
        __syncthreads();
    }

    const int mrow  = m0 + wm * 64 + (lane >> 2);
    const int ncol0 = n0 + wn * 32 + (lane & 3) * 2;
#pragma unroll
    for (int mt = 0; mt < 4; mt++) {
#pragma unroll
        for (int nt = 0; nt < 4; nt++) {
            int cc = ncol0 + nt * 8;
            if (cc < N) {
                float b0v = bias0[cc], b1v = bias0[cc + 1];
                if (bias1) { b0v += bias1[cc]; b1v += bias1[cc + 1]; }
                int r0 = mrow + mt * 16;
                float2 v0 = make_float2(acc[mt][nt][0] + b0v, acc[mt][nt][1] + b1v);
                float2 v1 = make_float2(acc[mt][nt][2] + b0v, acc[mt][nt][3] + b1v);
                *(float2*)(C + (size_t)r0 * N + cc)       = v0;
                *(float2*)(C + (size_t)(r0 + 8) * N + cc) = v1;
            }
        }
    }
#undef PREFETCH
}

// ---------------- persistent LSTM, tensor-core recurrence ----------------------
// 64 CTAs x 256 threads (8 warps). CTA owns 8 hidden units -> 32 gate rows.
// W_hh rows (fp16) SMEM-resident for all steps. h state: fp16 [32 x 512]
// ping-pong in global (L2). Per step: cp.async-stage h, HMMA [32x32x512],
// fp32 pointwise (c in SMEM), grid barrier.
#define LWS_OFF  0
#define LHS_OFF  32768
#define LGSM_OFF 65536
#define LCSM_OFF (65536 + 32 * 33 * 4)
#define LSM_BYTES (LCSM_OFF + 256 * 4)

__device__ __forceinline__ float sigf(float x) { return 1.0f / (1.0f + expf(-x)); }

__global__ __launch_bounds__(256, 1) void lstm_persistent(
    const float* __restrict__ pregates,
    const __half* __restrict__ Whh2,
    __half* __restrict__ hA, __half* __restrict__ hB,
    __half* __restrict__ H2, int* __restrict__ bar)
{
    extern __shared__ char smem[];
    const uint32_t sb = smem_u32(smem);
    float* gsm = (float*)(smem + LGSM_OFF);
    float* csm = (float*)(smem + LCSM_OFF);

    const int tid  = threadIdx.x;
    const int lane = tid & 31, wid = tid >> 5;
    const int u0   = blockIdx.x * 8;

    // stage 32 gate rows of W_hh (fp16) once: rr = g*8+ul <-> global g*512+u0+ul
    for (int i = tid; i < 2048; i += 256) {
        int rr = i >> 6, cq = i & 63;
        int g = rr >> 3, ul = rr & 7;
        uint32_t dst = sb + LWS_OFF + (uint32_t)(rr * 1024 + ((cq * 16) ^ ((rr & 7) * 16)));
        cpasync16(dst, Whh2 + (size_t)(g * 512 + u0 + ul) * HID + cq * 8);
    }
    CP_COMMIT();
    csm[tid] = 0.0f;

    // warp geometry: wm = m16 tile (0/1), wn = n8 tile (0..3)
    const int wm = wid & 1, wn = wid >> 1;
    const int rowA = wm * 16 + (lane & 15);
    const int kxA  = (lane >> 4) * 16;
    const int sxA  = (rowA & 7) * 16;
    const int rowB = wn * 8 + (lane & 7);
    const int kxB  = ((lane >> 3) & 3) * 16;
    const int sxB  = (rowB & 7) * 16;
    const uint32_t wsb = sb + LWS_OFF, hsb = sb + LHS_OFF;

    // pointwise mapping: tid -> (b = tid>>3, ul = tid&7)
    const int pb = tid >> 3, pul = tid & 7;
    const int pu = u0 + pul;

    for (int t = 0; t < TT; t++) {
        // stage h (fp16 32x512) into swizzled SMEM
        const __half* hin = (t & 1) ? hB : hA;
        for (int i = tid; i < 2048; i += 256) {
            int b = i >> 6, cq = i & 63;
            uint32_t dst = hsb + (uint32_t)(b * 1024 + ((cq * 16) ^ ((b & 7) * 16)));
            cpasync16(dst, hin + b * HID + cq * 8);
        }
        CP_COMMIT();
        CP_WAIT0();
        __syncthreads();

        // MMA: [32 gate-rows x 32 batch] = Ws[32x512] * hs[32x512]^T
        float c0[4] = {0.f, 0.f, 0.f, 0.f}, c1[4] = {0.f, 0.f, 0.f, 0.f};
#pragma unroll
        for (int ks2 = 0; ks2 < 16; ks2++) {
            uint32_t bf[4], a0[4], a1[4];
            ldsm4(bf, hsb + (uint32_t)(rowB * 1024 + ((ks2 * 64 + kxB) ^ sxB)));
            ldsm4(a0, wsb + (uint32_t)(rowA * 1024 + ((ks2 * 64 + kxA) ^ sxA)));
            ldsm4(a1, wsb + (uint32_t)(rowA * 1024 + ((ks2 * 64 + 32 + kxA) ^ sxA)));
            mma16816(c0, a0, bf[0], bf[1]);
            mma16816(c1, a1, bf[2], bf[3]);
        }
#pragma unroll
        for (int e = 0; e < 4; e++) c0[e] += c1[e];
        // write to gsm[row][batch], pitch 33
        {
            int r0 = wm * 16 + (lane >> 2);
            int cc = wn * 8 + (lane & 3) * 2;
            gsm[r0 * 33 + cc]           = c0[0];
            gsm[r0 * 33 + cc + 1]       = c0[1];
            gsm[(r0 + 8) * 33 + cc]     = c0[2];
            gsm[(r0 + 8) * 33 + cc + 1] = c0[3];
        }
        __syncthreads();

        // pointwise: 256 threads = 32 b x 8 units
        {
            size_t pg = ((size_t)pb * TT + t) * G4 + pu;
            float gi = gsm[(0  + pul) * 33 + pb] + pregates[pg];
            float gf = gsm[(8  + pul) * 33 + pb] + pregates[pg + 512];
            float gg = gsm[(16 + pul) * 33 + pb] + pregates[pg + 1024];
            float go = gsm[(24 + pul) * 33 + pb] + pregates[pg + 1536];
            float c_old = csm[tid];
            float cn = sigf(gf) * c_old + sigf(gi) * tanhf(gg);
            float hn = sigf(go) * tanhf(cn);
            csm[tid] = cn;
            __half hh = __float2half(hn);
            __half* hout = (t & 1) ? hA : hB;
            hout[pb * HID + pu] = hh;
            H2[((size_t)pb * TT + t) * HID + pu] = hh;
        }

        if (t < TT - 1) {
            __threadfence();
            __syncthreads();
            if (tid == 0) {
                atomicAdd(bar, 1);
                int target = 64 * (t + 1);
                while (*((volatile int*)bar) < target) { }
            }
            __syncthreads();
            __threadfence();
        }
    }
}

// ---------------- launch ------------------------------------------------------
extern "C" void kernel_launch(void* const* d_in, const int* in_sizes, int n_in,
                              void* d_out, int out_size)
{
    const float* enc       = (const float*)d_in[0];
    const int*   captions  = (const int*)  d_in[1];
    const float* emb_table = (const float*)d_in[8];
    const float* W_ih      = (const float*)d_in[9];
    const float* W_hh      = (const float*)d_in[10];
    const float* b_ih      = (const float*)d_in[11];
    const float* b_hh      = (const float*)d_in[12];
    const float* W_fc      = (const float*)d_in[13];
    const float* b_fc      = (const float*)d_in[14];
    float* out = (float*)d_out;

    __half *pX2, *pWih2, *pWhh2, *pWfc2, *pH2, *ph2A, *ph2B;
    float *pPG;
    int* pBar;
    cudaGetSymbolAddress((void**)&pX2, g_X2);
    cudaGetSymbolAddress((void**)&pWih2, g_Wih2);
    cudaGetSymbolAddress((void**)&pWhh2, g_Whh2);
    cudaGetSymbolAddress((void**)&pWfc2, g_Wfc2);
    cudaGetSymbolAddress((void**)&pH2, g_H2);
    cudaGetSymbolAddress((void**)&ph2A, g_h2A);
    cudaGetSymbolAddress((void**)&ph2B, g_h2B);
    cudaGetSymbolAddress((void**)&pPG, g_pg);
    cudaGetSymbolAddress((void**)&pBar, g_bar);

    cudaFuncSetAttribute(hmma_gemm, cudaFuncAttributeMaxDynamicSharedMemorySize, GSMEM);
    cudaFuncSetAttribute(lstm_persistent, cudaFuncAttributeMaxDynamicSharedMemorySize, LSM_BYTES);

    // 1) fp32 -> fp16 weight converts
    cvt2h_kernel<<<(G4 * XD / 2 + 255) / 256, 256>>>(W_ih, pWih2, G4 * XD / 2);
    cvt2h_kernel<<<(G4 * HID / 2 + 255) / 256, 256>>>(W_hh, pWhh2, G4 * HID / 2);
    cvt2h_kernel<<<(VV * HID / 2 + 255) / 256, 256>>>(W_fc, pWfc2, VV * HID / 2);

    // 2) build X2, zero FULL h ping (8192 uint32 -> 32 blocks) + barrier reset
    prep_kernel<<<MROWS + 32, 256>>>(enc, captions, emb_table, pX2, ph2A, pBar);

    // 3) pregates = X @ W_ih^T + b_ih + b_hh   (K = 768)
    {
        dim3 grid(G4 / 128, MROWS / 128);
        hmma_gemm<<<grid, 256, GSMEM>>>(pX2, pWih2, pPG, b_ih, b_hh,
                                        MROWS, G4, XD);
    }

    // 4) persistent tensor-core LSTM (one launch, emits H2 inline)
    lstm_persistent<<<64, 256, LSM_BYTES>>>(pPG, pWhh2, ph2A, ph2B, pH2, pBar);

    // 5) out = H @ W_fc^T + b_fc   (K = 512)
    {
        dim3 grid((VV + 127) / 128, MROWS / 128);
        hmma_gemm<<<grid, 256, GSMEM>>>(pH2, pWfc2, out, b_fc, nullptr,
                                        MROWS, VV, HID);
    }
}